// round 6
// baseline (speedup 1.0000x reference)
#include <cuda_runtime.h>
#include <math.h>

#define BATCH 4
#define SEQ   2048
#define EMB   1024
#define ADIM  1024

// Scratch (device globals are the sanctioned alloc-free scratch mechanism)
__device__ float g_Q[(size_t)BATCH * SEQ * ADIM];   // 32 MB
__device__ float g_K[(size_t)BATCH * SEQ * ADIM];   // 32 MB
__device__ float g_V[(size_t)BATCH * SEQ * ADIM];   // 32 MB
__device__ float g_S[(size_t)BATCH * SEQ * SEQ];    // 64 MB (scores, then probs in-place)

// ---------------------------------------------------------------------------
// NT GEMM: C[m,n] = alpha * sum_k A[m,k] * B[n,k]
// A: [M,K] row-major, B: [N,K] row-major, C: [M,N] row-major.
// causal: skip tiles fully above the diagonal (bn > bm). M,N,K multiples of 128/16.
// ---------------------------------------------------------------------------
__global__ __launch_bounds__(256, 2)
void gemm_nt_kernel(float* __restrict__ C, const float* __restrict__ A,
                    const float* __restrict__ B,
                    int M, int N, int K, float alpha, int causal,
                    long long sA, long long sB, long long sC)
{
    constexpr int BM = 128, BN = 128, BK = 16, LDSM = BM + 4;
    __shared__ float As[2][BK][LDSM];
    __shared__ float Bs[2][BK][LDSM];

    const int bn = blockIdx.x, bm = blockIdx.y, bz = blockIdx.z;
    if (causal && bn > bm) return;   // entire tile strictly above diagonal: never read

    A += (long long)bz * sA + (long long)bm * BM * K;
    B += (long long)bz * sB + (long long)bn * BN * K;
    C += (long long)bz * sC;

    const int tid = threadIdx.x;
    const int tx = tid & 15, ty = tid >> 4;
    const int lr = tid >> 2;            // 0..63 (row within tile, +64 on 2nd pass)
    const int lc = (tid & 3) << 2;      // 0,4,8,12 (k-col within tile)

    float acc[8][8];
#pragma unroll
    for (int i = 0; i < 8; i++)
#pragma unroll
        for (int j = 0; j < 8; j++) acc[i][j] = 0.0f;

    // prologue: tile 0
#pragma unroll
    for (int i = 0; i < 2; i++) {
        const int r = lr + i * 64;
        const float4 a4 = *reinterpret_cast<const float4*>(A + (long long)r * K + lc);
        As[0][lc + 0][r] = a4.x; As[0][lc + 1][r] = a4.y;
        As[0][lc + 2][r] = a4.z; As[0][lc + 3][r] = a4.w;
        const float4 b4 = *reinterpret_cast<const float4*>(B + (long long)r * K + lc);
        Bs[0][lc + 0][r] = b4.x; Bs[0][lc + 1][r] = b4.y;
        Bs[0][lc + 2][r] = b4.z; Bs[0][lc + 3][r] = b4.w;
    }
    __syncthreads();

    const int NT = K / BK;
    int buf = 0;
    for (int t = 0; t < NT; t++) {
        float4 pa[2], pb[2];
        const bool hasNext = (t + 1 < NT);
        if (hasNext) {
            const int k0 = (t + 1) * BK;
#pragma unroll
            for (int i = 0; i < 2; i++) {
                const int r = lr + i * 64;
                pa[i] = *reinterpret_cast<const float4*>(A + (long long)r * K + k0 + lc);
                pb[i] = *reinterpret_cast<const float4*>(B + (long long)r * K + k0 + lc);
            }
        }
#pragma unroll
        for (int kk = 0; kk < BK; kk++) {
            float af[8], bf[8];
            *reinterpret_cast<float4*>(&af[0]) = *reinterpret_cast<const float4*>(&As[buf][kk][ty * 4]);
            *reinterpret_cast<float4*>(&af[4]) = *reinterpret_cast<const float4*>(&As[buf][kk][64 + ty * 4]);
            *reinterpret_cast<float4*>(&bf[0]) = *reinterpret_cast<const float4*>(&Bs[buf][kk][tx * 4]);
            *reinterpret_cast<float4*>(&bf[4]) = *reinterpret_cast<const float4*>(&Bs[buf][kk][64 + tx * 4]);
#pragma unroll
            for (int i = 0; i < 8; i++)
#pragma unroll
                for (int j = 0; j < 8; j++)
                    acc[i][j] = fmaf(af[i], bf[j], acc[i][j]);
        }
        if (hasNext) {
            const int nb = buf ^ 1;
#pragma unroll
            for (int i = 0; i < 2; i++) {
                const int r = lr + i * 64;
                As[nb][lc + 0][r] = pa[i].x; As[nb][lc + 1][r] = pa[i].y;
                As[nb][lc + 2][r] = pa[i].z; As[nb][lc + 3][r] = pa[i].w;
                Bs[nb][lc + 0][r] = pb[i].x; Bs[nb][lc + 1][r] = pb[i].y;
                Bs[nb][lc + 2][r] = pb[i].z; Bs[nb][lc + 3][r] = pb[i].w;
            }
        }
        __syncthreads();
        buf ^= 1;
    }

    const int rbase = bm * BM, cbase = bn * BN;
#pragma unroll
    for (int i = 0; i < 8; i++) {
        const int r = rbase + ((i < 4) ? (ty * 4 + i) : (64 + ty * 4 + i - 4));
        float4 v0, v1;
        v0.x = acc[i][0] * alpha; v0.y = acc[i][1] * alpha;
        v0.z = acc[i][2] * alpha; v0.w = acc[i][3] * alpha;
        v1.x = acc[i][4] * alpha; v1.y = acc[i][5] * alpha;
        v1.z = acc[i][6] * alpha; v1.w = acc[i][7] * alpha;
        *reinterpret_cast<float4*>(C + (long long)r * N + cbase + tx * 4) = v0;
        *reinterpret_cast<float4*>(C + (long long)r * N + cbase + 64 + tx * 4) = v1;
    }
}

// ---------------------------------------------------------------------------
// NN GEMM with causal k-limit + round-to-4-decimals epilogue:
// C[m,n] = round4( sum_{k<kend} A[m,k] * B[k,n] ),  kend = (bm+1)*BM (<=K)
// A: [M,K] row-major (probs), B: [K,N] row-major (V), C: [M,N] row-major.
// ---------------------------------------------------------------------------
__global__ __launch_bounds__(256, 2)
void gemm_nn_round_kernel(float* __restrict__ C, const float* __restrict__ A,
                          const float* __restrict__ B,
                          int M, int N, int K, int causal,
                          long long sA, long long sB, long long sC)
{
    constexpr int BM = 128, BN = 128, BK = 16, LDSM = BM + 4;
    __shared__ float As[2][BK][LDSM];
    __shared__ float Bs[2][BK][LDSM];

    const int bn = blockIdx.x, bm = blockIdx.y, bz = blockIdx.z;

    A += (long long)bz * sA + (long long)bm * BM * K;
    B += (long long)bz * sB;
    C += (long long)bz * sC;

    const int tid = threadIdx.x;
    const int tx = tid & 15, ty = tid >> 4;
    const int lr = tid >> 2;
    const int lc = (tid & 3) << 2;
    const int brow = tid >> 5;          // 0..7
    const int bcol = (tid & 31) << 2;   // 0..124

    const int kend = causal ? ((bm + 1) * BM < K ? (bm + 1) * BM : K) : K;
    const int NT = kend / BK;

    float acc[8][8];
#pragma unroll
    for (int i = 0; i < 8; i++)
#pragma unroll
        for (int j = 0; j < 8; j++) acc[i][j] = 0.0f;

    // prologue: tile 0
#pragma unroll
    for (int i = 0; i < 2; i++) {
        const int r = lr + i * 64;
        const float4 a4 = *reinterpret_cast<const float4*>(A + (long long)r * K + lc);
        As[0][lc + 0][r] = a4.x; As[0][lc + 1][r] = a4.y;
        As[0][lc + 2][r] = a4.z; As[0][lc + 3][r] = a4.w;
        const int kr = brow + i * 8;
        const float4 b4 = *reinterpret_cast<const float4*>(
            B + (long long)kr * N + (long long)bn * BN + bcol);
        *reinterpret_cast<float4*>(&Bs[0][kr][bcol]) = b4;
    }
    __syncthreads();

    int buf = 0;
    for (int t = 0; t < NT; t++) {
        float4 pa[2], pb[2];
        const bool hasNext = (t + 1 < NT);
        if (hasNext) {
            const int k0 = (t + 1) * BK;
#pragma unroll
            for (int i = 0; i < 2; i++) {
                pa[i] = *reinterpret_cast<const float4*>(
                    A + (long long)(lr + i * 64) * K + k0 + lc);
                pb[i] = *reinterpret_cast<const float4*>(
                    B + (long long)(k0 + brow + i * 8) * N + (long long)bn * BN + bcol);
            }
        }
#pragma unroll
        for (int kk = 0; kk < BK; kk++) {
            float af[8], bf[8];
            *reinterpret_cast<float4*>(&af[0]) = *reinterpret_cast<const float4*>(&As[buf][kk][ty * 4]);
            *reinterpret_cast<float4*>(&af[4]) = *reinterpret_cast<const float4*>(&As[buf][kk][64 + ty * 4]);
            *reinterpret_cast<float4*>(&bf[0]) = *reinterpret_cast<const float4*>(&Bs[buf][kk][tx * 4]);
            *reinterpret_cast<float4*>(&bf[4]) = *reinterpret_cast<const float4*>(&Bs[buf][kk][64 + tx * 4]);
#pragma unroll
            for (int i = 0; i < 8; i++)
#pragma unroll
                for (int j = 0; j < 8; j++)
                    acc[i][j] = fmaf(af[i], bf[j], acc[i][j]);
        }
        if (hasNext) {
            const int nb = buf ^ 1;
#pragma unroll
            for (int i = 0; i < 2; i++) {
                const int r = lr + i * 64;
                As[nb][lc + 0][r] = pa[i].x; As[nb][lc + 1][r] = pa[i].y;
                As[nb][lc + 2][r] = pa[i].z; As[nb][lc + 3][r] = pa[i].w;
                *reinterpret_cast<float4*>(&Bs[nb][brow + i * 8][bcol]) = pb[i];
            }
        }
        __syncthreads();
        buf ^= 1;
    }

    const int rbase = bm * BM, cbase = bn * BN;
#pragma unroll
    for (int i = 0; i < 8; i++) {
        const int r = rbase + ((i < 4) ? (ty * 4 + i) : (64 + ty * 4 + i - 4));
        float4 v0, v1;
        // round-half-even to 4 decimals, exactly as jnp.round(x,4): rint(x*1e4)/1e4
        v0.x = rintf(acc[i][0] * 10000.0f) / 10000.0f;
        v0.y = rintf(acc[i][1] * 10000.0f) / 10000.0f;
        v0.z = rintf(acc[i][2] * 10000.0f) / 10000.0f;
        v0.w = rintf(acc[i][3] * 10000.0f) / 10000.0f;
        v1.x = rintf(acc[i][4] * 10000.0f) / 10000.0f;
        v1.y = rintf(acc[i][5] * 10000.0f) / 10000.0f;
        v1.z = rintf(acc[i][6] * 10000.0f) / 10000.0f;
        v1.w = rintf(acc[i][7] * 10000.0f) / 10000.0f;
        *reinterpret_cast<float4*>(C + (long long)r * N + cbase + tx * 4) = v0;
        *reinterpret_cast<float4*>(C + (long long)r * N + cbase + 64 + tx * 4) = v1;
    }
}

// ---------------------------------------------------------------------------
// Causal softmax over row q (valid length q+1), in place; zero-fills the masked
// tail so the P*V GEMM can run dense tiles. One block (256 thr) per row.
// ---------------------------------------------------------------------------
__global__ void softmax_kernel(float* __restrict__ S)
{
    const int q = blockIdx.x;
    const int b = blockIdx.y;
    float* row = S + ((long long)b * SEQ + q) * (long long)SEQ;
    const int L = q + 1;
    const int t = threadIdx.x;
    const float NEG_INF = __int_as_float(0xff800000u);

    float xv[8];
    float m = NEG_INF;
#pragma unroll
    for (int i = 0; i < 8; i++) {
        const int idx = i * 256 + t;
        xv[i] = (idx < L) ? row[idx] : NEG_INF;
        m = fmaxf(m, xv[i]);
    }
#pragma unroll
    for (int o = 16; o > 0; o >>= 1) m = fmaxf(m, __shfl_xor_sync(0xffffffffu, m, o));

    __shared__ float smax[8], ssum[8];
    if ((t & 31) == 0) smax[t >> 5] = m;
    __syncthreads();
    float mm = smax[0];
#pragma unroll
    for (int w = 1; w < 8; w++) mm = fmaxf(mm, smax[w]);

    float e[8];
    float s = 0.0f;
#pragma unroll
    for (int i = 0; i < 8; i++) { e[i] = expf(xv[i] - mm); s += e[i]; }  // exp(-inf)=0 masks
#pragma unroll
    for (int o = 16; o > 0; o >>= 1) s += __shfl_xor_sync(0xffffffffu, s, o);
    if ((t & 31) == 0) ssum[t >> 5] = s;
    __syncthreads();
    float ss = 0.0f;
#pragma unroll
    for (int w = 0; w < 8; w++) ss += ssum[w];

#pragma unroll
    for (int i = 0; i < 8; i++) {
        const int idx = i * 256 + t;
        row[idx] = (idx < L) ? (e[i] / ss) : 0.0f;
    }
}

// ---------------------------------------------------------------------------
extern "C" void kernel_launch(void* const* d_in, const int* in_sizes, int n_in,
                              void* d_out, int out_size)
{
    const float* X  = (const float*)d_in[0];  // embedded [4,2048,1024]
    const float* Wk = (const float*)d_in[1];  // [1024,1024]
    const float* Wq = (const float*)d_in[2];
    const float* Wv = (const float*)d_in[3];
    float* out = (float*)d_out;               // [4,2048,1024] fp32

    float *Qp, *Kp, *Vp, *Sp;
    cudaGetSymbolAddress((void**)&Qp, g_Q);
    cudaGetSymbolAddress((void**)&Kp, g_K);
    cudaGetSymbolAddress((void**)&Vp, g_V);
    cudaGetSymbolAddress((void**)&Sp, g_S);

    const dim3 blk(256);
    const long long sQKV = (long long)SEQ * ADIM;
    const long long sS   = (long long)SEQ * SEQ;

    // 1-3) Projections: [8192,1024] = X[8192,1024] * W^T (NT GEMM)
    const dim3 gproj(ADIM / 128, (BATCH * SEQ) / 128, 1);
    gemm_nt_kernel<<<gproj, blk>>>(Qp, X, Wq, BATCH * SEQ, ADIM, EMB, 1.0f, 0, 0, 0, 0);
    gemm_nt_kernel<<<gproj, blk>>>(Kp, X, Wk, BATCH * SEQ, ADIM, EMB, 1.0f, 0, 0, 0, 0);
    gemm_nt_kernel<<<gproj, blk>>>(Vp, X, Wv, BATCH * SEQ, ADIM, EMB, 1.0f, 0, 0, 0, 0);

    // 4) Scores: S_b = (1/32) * Q_b * K_b^T, causal tile-skip
    const dim3 gs(SEQ / 128, SEQ / 128, BATCH);
    gemm_nt_kernel<<<gs, blk>>>(Sp, Qp, Kp, SEQ, SEQ, ADIM, 0.03125f, 1, sQKV, sQKV, sS);

    // 5) Causal softmax (in place, zero-fills masked tail)
    softmax_kernel<<<dim3(SEQ, BATCH), blk>>>(Sp);

    // 6) Out = round4(P_b * V_b), causal k-loop truncation
    const dim3 go(ADIM / 128, SEQ / 128, BATCH);
    gemm_nn_round_kernel<<<go, blk>>>(out, Sp, Vp, SEQ, ADIM, SEQ, 1, sS, sQKV, sQKV);
}

// round 7
// speedup vs baseline: 1.0002x; 1.0002x over previous
#include <cuda_runtime.h>
#include <math.h>

#define BATCH 4
#define SEQ   2048
#define EMB   1024
#define ADIM  1024

// Scratch (device globals are the sanctioned alloc-free scratch mechanism)
__device__ float g_Q[(size_t)BATCH * SEQ * ADIM];   // 32 MB
__device__ float g_K[(size_t)BATCH * SEQ * ADIM];   // 32 MB
__device__ float g_V[(size_t)BATCH * SEQ * ADIM];   // 32 MB
__device__ float g_S[(size_t)BATCH * SEQ * SEQ];    // 64 MB (scores, then probs in-place)

// ---------------------------------------------------------------------------
// NT GEMM: C[m,n] = alpha * sum_k A[m,k] * B[n,k]
// A: [M,K] row-major, B: [N,K] row-major, C: [M,N] row-major.
// causal: skip tiles fully above the diagonal (bn > bm). M,N,K multiples of 128/16.
// ---------------------------------------------------------------------------
__global__ __launch_bounds__(256, 2)
void gemm_nt_kernel(float* __restrict__ C, const float* __restrict__ A,
                    const float* __restrict__ B,
                    int M, int N, int K, float alpha, int causal,
                    long long sA, long long sB, long long sC)
{
    constexpr int BM = 128, BN = 128, BK = 16, LDSM = BM + 4;
    __shared__ float As[2][BK][LDSM];
    __shared__ float Bs[2][BK][LDSM];

    const int bn = blockIdx.x, bm = blockIdx.y, bz = blockIdx.z;
    if (causal && bn > bm) return;   // entire tile strictly above diagonal: never read

    A += (long long)bz * sA + (long long)bm * BM * K;
    B += (long long)bz * sB + (long long)bn * BN * K;
    C += (long long)bz * sC;

    const int tid = threadIdx.x;
    const int tx = tid & 15, ty = tid >> 4;
    const int lr = tid >> 2;            // 0..63 (row within tile, +64 on 2nd pass)
    const int lc = (tid & 3) << 2;      // 0,4,8,12 (k-col within tile)

    float acc[8][8];
#pragma unroll
    for (int i = 0; i < 8; i++)
#pragma unroll
        for (int j = 0; j < 8; j++) acc[i][j] = 0.0f;

    // prologue: tile 0
#pragma unroll
    for (int i = 0; i < 2; i++) {
        const int r = lr + i * 64;
        const float4 a4 = *reinterpret_cast<const float4*>(A + (long long)r * K + lc);
        As[0][lc + 0][r] = a4.x; As[0][lc + 1][r] = a4.y;
        As[0][lc + 2][r] = a4.z; As[0][lc + 3][r] = a4.w;
        const float4 b4 = *reinterpret_cast<const float4*>(B + (long long)r * K + lc);
        Bs[0][lc + 0][r] = b4.x; Bs[0][lc + 1][r] = b4.y;
        Bs[0][lc + 2][r] = b4.z; Bs[0][lc + 3][r] = b4.w;
    }
    __syncthreads();

    const int NT = K / BK;
    int buf = 0;
    for (int t = 0; t < NT; t++) {
        float4 pa[2], pb[2];
        const bool hasNext = (t + 1 < NT);
        if (hasNext) {
            const int k0 = (t + 1) * BK;
#pragma unroll
            for (int i = 0; i < 2; i++) {
                const int r = lr + i * 64;
                pa[i] = *reinterpret_cast<const float4*>(A + (long long)r * K + k0 + lc);
                pb[i] = *reinterpret_cast<const float4*>(B + (long long)r * K + k0 + lc);
            }
        }
#pragma unroll
        for (int kk = 0; kk < BK; kk++) {
            float af[8], bf[8];
            *reinterpret_cast<float4*>(&af[0]) = *reinterpret_cast<const float4*>(&As[buf][kk][ty * 4]);
            *reinterpret_cast<float4*>(&af[4]) = *reinterpret_cast<const float4*>(&As[buf][kk][64 + ty * 4]);
            *reinterpret_cast<float4*>(&bf[0]) = *reinterpret_cast<const float4*>(&Bs[buf][kk][tx * 4]);
            *reinterpret_cast<float4*>(&bf[4]) = *reinterpret_cast<const float4*>(&Bs[buf][kk][64 + tx * 4]);
#pragma unroll
            for (int i = 0; i < 8; i++)
#pragma unroll
                for (int j = 0; j < 8; j++)
                    acc[i][j] = fmaf(af[i], bf[j], acc[i][j]);
        }
        if (hasNext) {
            const int nb = buf ^ 1;
#pragma unroll
            for (int i = 0; i < 2; i++) {
                const int r = lr + i * 64;
                As[nb][lc + 0][r] = pa[i].x; As[nb][lc + 1][r] = pa[i].y;
                As[nb][lc + 2][r] = pa[i].z; As[nb][lc + 3][r] = pa[i].w;
                Bs[nb][lc + 0][r] = pb[i].x; Bs[nb][lc + 1][r] = pb[i].y;
                Bs[nb][lc + 2][r] = pb[i].z; Bs[nb][lc + 3][r] = pb[i].w;
            }
        }
        __syncthreads();
        buf ^= 1;
    }

    const int rbase = bm * BM, cbase = bn * BN;
#pragma unroll
    for (int i = 0; i < 8; i++) {
        const int r = rbase + ((i < 4) ? (ty * 4 + i) : (64 + ty * 4 + i - 4));
        float4 v0, v1;
        v0.x = acc[i][0] * alpha; v0.y = acc[i][1] * alpha;
        v0.z = acc[i][2] * alpha; v0.w = acc[i][3] * alpha;
        v1.x = acc[i][4] * alpha; v1.y = acc[i][5] * alpha;
        v1.z = acc[i][6] * alpha; v1.w = acc[i][7] * alpha;
        *reinterpret_cast<float4*>(C + (long long)r * N + cbase + tx * 4) = v0;
        *reinterpret_cast<float4*>(C + (long long)r * N + cbase + 64 + tx * 4) = v1;
    }
}

// ---------------------------------------------------------------------------
// NN GEMM with causal k-limit + round-to-4-decimals epilogue:
// C[m,n] = round4( sum_{k<kend} A[m,k] * B[k,n] ),  kend = (bm+1)*BM (<=K)
// A: [M,K] row-major (probs), B: [K,N] row-major (V), C: [M,N] row-major.
// ---------------------------------------------------------------------------
__global__ __launch_bounds__(256, 2)
void gemm_nn_round_kernel(float* __restrict__ C, const float* __restrict__ A,
                          const float* __restrict__ B,
                          int M, int N, int K, int causal,
                          long long sA, long long sB, long long sC)
{
    constexpr int BM = 128, BN = 128, BK = 16, LDSM = BM + 4;
    __shared__ float As[2][BK][LDSM];
    __shared__ float Bs[2][BK][LDSM];

    const int bn = blockIdx.x, bm = blockIdx.y, bz = blockIdx.z;

    A += (long long)bz * sA + (long long)bm * BM * K;
    B += (long long)bz * sB;
    C += (long long)bz * sC;

    const int tid = threadIdx.x;
    const int tx = tid & 15, ty = tid >> 4;
    const int lr = tid >> 2;
    const int lc = (tid & 3) << 2;
    const int brow = tid >> 5;          // 0..7
    const int bcol = (tid & 31) << 2;   // 0..124

    const int kend = causal ? ((bm + 1) * BM < K ? (bm + 1) * BM : K) : K;
    const int NT = kend / BK;

    float acc[8][8];
#pragma unroll
    for (int i = 0; i < 8; i++)
#pragma unroll
        for (int j = 0; j < 8; j++) acc[i][j] = 0.0f;

    // prologue: tile 0
#pragma unroll
    for (int i = 0; i < 2; i++) {
        const int r = lr + i * 64;
        const float4 a4 = *reinterpret_cast<const float4*>(A + (long long)r * K + lc);
        As[0][lc + 0][r] = a4.x; As[0][lc + 1][r] = a4.y;
        As[0][lc + 2][r] = a4.z; As[0][lc + 3][r] = a4.w;
        const int kr = brow + i * 8;
        const float4 b4 = *reinterpret_cast<const float4*>(
            B + (long long)kr * N + (long long)bn * BN + bcol);
        *reinterpret_cast<float4*>(&Bs[0][kr][bcol]) = b4;
    }
    __syncthreads();

    int buf = 0;
    for (int t = 0; t < NT; t++) {
        float4 pa[2], pb[2];
        const bool hasNext = (t + 1 < NT);
        if (hasNext) {
            const int k0 = (t + 1) * BK;
#pragma unroll
            for (int i = 0; i < 2; i++) {
                pa[i] = *reinterpret_cast<const float4*>(
                    A + (long long)(lr + i * 64) * K + k0 + lc);
                pb[i] = *reinterpret_cast<const float4*>(
                    B + (long long)(k0 + brow + i * 8) * N + (long long)bn * BN + bcol);
            }
        }
#pragma unroll
        for (int kk = 0; kk < BK; kk++) {
            float af[8], bf[8];
            *reinterpret_cast<float4*>(&af[0]) = *reinterpret_cast<const float4*>(&As[buf][kk][ty * 4]);
            *reinterpret_cast<float4*>(&af[4]) = *reinterpret_cast<const float4*>(&As[buf][kk][64 + ty * 4]);
            *reinterpret_cast<float4*>(&bf[0]) = *reinterpret_cast<const float4*>(&Bs[buf][kk][tx * 4]);
            *reinterpret_cast<float4*>(&bf[4]) = *reinterpret_cast<const float4*>(&Bs[buf][kk][64 + tx * 4]);
#pragma unroll
            for (int i = 0; i < 8; i++)
#pragma unroll
                for (int j = 0; j < 8; j++)
                    acc[i][j] = fmaf(af[i], bf[j], acc[i][j]);
        }
        if (hasNext) {
            const int nb = buf ^ 1;
#pragma unroll
            for (int i = 0; i < 2; i++) {
                const int r = lr + i * 64;
                As[nb][lc + 0][r] = pa[i].x; As[nb][lc + 1][r] = pa[i].y;
                As[nb][lc + 2][r] = pa[i].z; As[nb][lc + 3][r] = pa[i].w;
                *reinterpret_cast<float4*>(&Bs[nb][brow + i * 8][bcol]) = pb[i];
            }
        }
        __syncthreads();
        buf ^= 1;
    }

    const int rbase = bm * BM, cbase = bn * BN;
#pragma unroll
    for (int i = 0; i < 8; i++) {
        const int r = rbase + ((i < 4) ? (ty * 4 + i) : (64 + ty * 4 + i - 4));
        float4 v0, v1;
        // round-half-even to 4 decimals, exactly as jnp.round(x,4): rint(x*1e4)/1e4
        v0.x = rintf(acc[i][0] * 10000.0f) / 10000.0f;
        v0.y = rintf(acc[i][1] * 10000.0f) / 10000.0f;
        v0.z = rintf(acc[i][2] * 10000.0f) / 10000.0f;
        v0.w = rintf(acc[i][3] * 10000.0f) / 10000.0f;
        v1.x = rintf(acc[i][4] * 10000.0f) / 10000.0f;
        v1.y = rintf(acc[i][5] * 10000.0f) / 10000.0f;
        v1.z = rintf(acc[i][6] * 10000.0f) / 10000.0f;
        v1.w = rintf(acc[i][7] * 10000.0f) / 10000.0f;
        *reinterpret_cast<float4*>(C + (long long)r * N + cbase + tx * 4) = v0;
        *reinterpret_cast<float4*>(C + (long long)r * N + cbase + 64 + tx * 4) = v1;
    }
}

// ---------------------------------------------------------------------------
// Causal softmax over row q (valid length q+1), in place; zero-fills the masked
// tail so the P*V GEMM can run dense tiles. One block (256 thr) per row.
// ---------------------------------------------------------------------------
__global__ void softmax_kernel(float* __restrict__ S)
{
    const int q = blockIdx.x;
    const int b = blockIdx.y;
    float* row = S + ((long long)b * SEQ + q) * (long long)SEQ;
    const int L = q + 1;
    const int t = threadIdx.x;
    const float NEG_INF = __int_as_float(0xff800000u);

    float xv[8];
    float m = NEG_INF;
#pragma unroll
    for (int i = 0; i < 8; i++) {
        const int idx = i * 256 + t;
        xv[i] = (idx < L) ? row[idx] : NEG_INF;
        m = fmaxf(m, xv[i]);
    }
#pragma unroll
    for (int o = 16; o > 0; o >>= 1) m = fmaxf(m, __shfl_xor_sync(0xffffffffu, m, o));

    __shared__ float smax[8], ssum[8];
    if ((t & 31) == 0) smax[t >> 5] = m;
    __syncthreads();
    float mm = smax[0];
#pragma unroll
    for (int w = 1; w < 8; w++) mm = fmaxf(mm, smax[w]);

    float e[8];
    float s = 0.0f;
#pragma unroll
    for (int i = 0; i < 8; i++) { e[i] = expf(xv[i] - mm); s += e[i]; }  // exp(-inf)=0 masks
#pragma unroll
    for (int o = 16; o > 0; o >>= 1) s += __shfl_xor_sync(0xffffffffu, s, o);
    if ((t & 31) == 0) ssum[t >> 5] = s;
    __syncthreads();
    float ss = 0.0f;
#pragma unroll
    for (int w = 0; w < 8; w++) ss += ssum[w];

#pragma unroll
    for (int i = 0; i < 8; i++) {
        const int idx = i * 256 + t;
        row[idx] = (idx < L) ? (e[i] / ss) : 0.0f;
    }
}

// ---------------------------------------------------------------------------
extern "C" void kernel_launch(void* const* d_in, const int* in_sizes, int n_in,
                              void* d_out, int out_size)
{
    const float* X  = (const float*)d_in[0];  // embedded [4,2048,1024]
    const float* Wk = (const float*)d_in[1];  // [1024,1024]
    const float* Wq = (const float*)d_in[2];
    const float* Wv = (const float*)d_in[3];
    float* out = (float*)d_out;               // [4,2048,1024] fp32

    float *Qp, *Kp, *Vp, *Sp;
    cudaGetSymbolAddress((void**)&Qp, g_Q);
    cudaGetSymbolAddress((void**)&Kp, g_K);
    cudaGetSymbolAddress((void**)&Vp, g_V);
    cudaGetSymbolAddress((void**)&Sp, g_S);

    const dim3 blk(256);
    const long long sQKV = (long long)SEQ * ADIM;
    const long long sS   = (long long)SEQ * SEQ;

    // 1-3) Projections: [8192,1024] = X[8192,1024] * W^T (NT GEMM)
    const dim3 gproj(ADIM / 128, (BATCH * SEQ) / 128, 1);
    gemm_nt_kernel<<<gproj, blk>>>(Qp, X, Wq, BATCH * SEQ, ADIM, EMB, 1.0f, 0, 0, 0, 0);
    gemm_nt_kernel<<<gproj, blk>>>(Kp, X, Wk, BATCH * SEQ, ADIM, EMB, 1.0f, 0, 0, 0, 0);
    gemm_nt_kernel<<<gproj, blk>>>(Vp, X, Wv, BATCH * SEQ, ADIM, EMB, 1.0f, 0, 0, 0, 0);

    // 4) Scores: S_b = (1/32) * Q_b * K_b^T, causal tile-skip
    const dim3 gs(SEQ / 128, SEQ / 128, BATCH);
    gemm_nt_kernel<<<gs, blk>>>(Sp, Qp, Kp, SEQ, SEQ, ADIM, 0.03125f, 1, sQKV, sQKV, sS);

    // 5) Causal softmax (in place, zero-fills masked tail)
    softmax_kernel<<<dim3(SEQ, BATCH), blk>>>(Sp);

    // 6) Out = round4(P_b * V_b), causal k-loop truncation
    const dim3 go(ADIM / 128, SEQ / 128, BATCH);
    gemm_nn_round_kernel<<<go, blk>>>(out, Sp, Vp, SEQ, ADIM, SEQ, 1, sS, sQKV, sQKV);
}

// round 8
// speedup vs baseline: 1.0019x; 1.0017x over previous
#include <cuda_runtime.h>
#include <math.h>

#define BATCH 4
#define SEQ   2048
#define EMB   1024
#define ADIM  1024

// Scratch (device globals are the sanctioned alloc-free scratch mechanism)
__device__ float g_Q[(size_t)BATCH * SEQ * ADIM];   // 32 MB
__device__ float g_K[(size_t)BATCH * SEQ * ADIM];   // 32 MB
__device__ float g_V[(size_t)BATCH * SEQ * ADIM];   // 32 MB
__device__ float g_S[(size_t)BATCH * SEQ * SEQ];    // 64 MB (scores, then probs in-place)

// ---------------------------------------------------------------------------
// NT GEMM: C[m,n] = alpha * sum_k A[m,k] * B[n,k]
// A: [M,K] row-major, B: [N,K] row-major, C: [M,N] row-major.
// causal: skip tiles fully above the diagonal (bn > bm). M,N,K multiples of 128/16.
// ---------------------------------------------------------------------------
__global__ __launch_bounds__(256, 2)
void gemm_nt_kernel(float* __restrict__ C, const float* __restrict__ A,
                    const float* __restrict__ B,
                    int M, int N, int K, float alpha, int causal,
                    long long sA, long long sB, long long sC)
{
    constexpr int BM = 128, BN = 128, BK = 16, LDSM = BM + 4;
    __shared__ float As[2][BK][LDSM];
    __shared__ float Bs[2][BK][LDSM];

    const int bn = blockIdx.x, bm = blockIdx.y, bz = blockIdx.z;
    if (causal && bn > bm) return;   // entire tile strictly above diagonal: never read

    A += (long long)bz * sA + (long long)bm * BM * K;
    B += (long long)bz * sB + (long long)bn * BN * K;
    C += (long long)bz * sC;

    const int tid = threadIdx.x;
    const int tx = tid & 15, ty = tid >> 4;
    const int lr = tid >> 2;            // 0..63 (row within tile, +64 on 2nd pass)
    const int lc = (tid & 3) << 2;      // 0,4,8,12 (k-col within tile)

    float acc[8][8];
#pragma unroll
    for (int i = 0; i < 8; i++)
#pragma unroll
        for (int j = 0; j < 8; j++) acc[i][j] = 0.0f;

    // prologue: tile 0
#pragma unroll
    for (int i = 0; i < 2; i++) {
        const int r = lr + i * 64;
        const float4 a4 = *reinterpret_cast<const float4*>(A + (long long)r * K + lc);
        As[0][lc + 0][r] = a4.x; As[0][lc + 1][r] = a4.y;
        As[0][lc + 2][r] = a4.z; As[0][lc + 3][r] = a4.w;
        const float4 b4 = *reinterpret_cast<const float4*>(B + (long long)r * K + lc);
        Bs[0][lc + 0][r] = b4.x; Bs[0][lc + 1][r] = b4.y;
        Bs[0][lc + 2][r] = b4.z; Bs[0][lc + 3][r] = b4.w;
    }
    __syncthreads();

    const int NT = K / BK;
    int buf = 0;
    for (int t = 0; t < NT; t++) {
        float4 pa[2], pb[2];
        const bool hasNext = (t + 1 < NT);
        if (hasNext) {
            const int k0 = (t + 1) * BK;
#pragma unroll
            for (int i = 0; i < 2; i++) {
                const int r = lr + i * 64;
                pa[i] = *reinterpret_cast<const float4*>(A + (long long)r * K + k0 + lc);
                pb[i] = *reinterpret_cast<const float4*>(B + (long long)r * K + k0 + lc);
            }
        }
#pragma unroll
        for (int kk = 0; kk < BK; kk++) {
            float af[8], bf[8];
            *reinterpret_cast<float4*>(&af[0]) = *reinterpret_cast<const float4*>(&As[buf][kk][ty * 4]);
            *reinterpret_cast<float4*>(&af[4]) = *reinterpret_cast<const float4*>(&As[buf][kk][64 + ty * 4]);
            *reinterpret_cast<float4*>(&bf[0]) = *reinterpret_cast<const float4*>(&Bs[buf][kk][tx * 4]);
            *reinterpret_cast<float4*>(&bf[4]) = *reinterpret_cast<const float4*>(&Bs[buf][kk][64 + tx * 4]);
#pragma unroll
            for (int i = 0; i < 8; i++)
#pragma unroll
                for (int j = 0; j < 8; j++)
                    acc[i][j] = fmaf(af[i], bf[j], acc[i][j]);
        }
        if (hasNext) {
            const int nb = buf ^ 1;
#pragma unroll
            for (int i = 0; i < 2; i++) {
                const int r = lr + i * 64;
                As[nb][lc + 0][r] = pa[i].x; As[nb][lc + 1][r] = pa[i].y;
                As[nb][lc + 2][r] = pa[i].z; As[nb][lc + 3][r] = pa[i].w;
                Bs[nb][lc + 0][r] = pb[i].x; Bs[nb][lc + 1][r] = pb[i].y;
                Bs[nb][lc + 2][r] = pb[i].z; Bs[nb][lc + 3][r] = pb[i].w;
            }
        }
        __syncthreads();
        buf ^= 1;
    }

    const int rbase = bm * BM, cbase = bn * BN;
#pragma unroll
    for (int i = 0; i < 8; i++) {
        const int r = rbase + ((i < 4) ? (ty * 4 + i) : (64 + ty * 4 + i - 4));
        float4 v0, v1;
        v0.x = acc[i][0] * alpha; v0.y = acc[i][1] * alpha;
        v0.z = acc[i][2] * alpha; v0.w = acc[i][3] * alpha;
        v1.x = acc[i][4] * alpha; v1.y = acc[i][5] * alpha;
        v1.z = acc[i][6] * alpha; v1.w = acc[i][7] * alpha;
        *reinterpret_cast<float4*>(C + (long long)r * N + cbase + tx * 4) = v0;
        *reinterpret_cast<float4*>(C + (long long)r * N + cbase + 64 + tx * 4) = v1;
    }
}

// ---------------------------------------------------------------------------
// NN GEMM with causal k-limit + round-to-4-decimals epilogue:
// C[m,n] = round4( sum_{k<kend} A[m,k] * B[k,n] ),  kend = (bm+1)*BM (<=K)
// A: [M,K] row-major (probs), B: [K,N] row-major (V), C: [M,N] row-major.
// ---------------------------------------------------------------------------
__global__ __launch_bounds__(256, 2)
void gemm_nn_round_kernel(float* __restrict__ C, const float* __restrict__ A,
                          const float* __restrict__ B,
                          int M, int N, int K, int causal,
                          long long sA, long long sB, long long sC)
{
    constexpr int BM = 128, BN = 128, BK = 16, LDSM = BM + 4;
    __shared__ float As[2][BK][LDSM];
    __shared__ float Bs[2][BK][LDSM];

    const int bn = blockIdx.x, bm = blockIdx.y, bz = blockIdx.z;

    A += (long long)bz * sA + (long long)bm * BM * K;
    B += (long long)bz * sB;
    C += (long long)bz * sC;

    const int tid = threadIdx.x;
    const int tx = tid & 15, ty = tid >> 4;
    const int lr = tid >> 2;
    const int lc = (tid & 3) << 2;
    const int brow = tid >> 5;          // 0..7
    const int bcol = (tid & 31) << 2;   // 0..124

    const int kend = causal ? ((bm + 1) * BM < K ? (bm + 1) * BM : K) : K;
    const int NT = kend / BK;

    float acc[8][8];
#pragma unroll
    for (int i = 0; i < 8; i++)
#pragma unroll
        for (int j = 0; j < 8; j++) acc[i][j] = 0.0f;

    // prologue: tile 0
#pragma unroll
    for (int i = 0; i < 2; i++) {
        const int r = lr + i * 64;
        const float4 a4 = *reinterpret_cast<const float4*>(A + (long long)r * K + lc);
        As[0][lc + 0][r] = a4.x; As[0][lc + 1][r] = a4.y;
        As[0][lc + 2][r] = a4.z; As[0][lc + 3][r] = a4.w;
        const int kr = brow + i * 8;
        const float4 b4 = *reinterpret_cast<const float4*>(
            B + (long long)kr * N + (long long)bn * BN + bcol);
        *reinterpret_cast<float4*>(&Bs[0][kr][bcol]) = b4;
    }
    __syncthreads();

    int buf = 0;
    for (int t = 0; t < NT; t++) {
        float4 pa[2], pb[2];
        const bool hasNext = (t + 1 < NT);
        if (hasNext) {
            const int k0 = (t + 1) * BK;
#pragma unroll
            for (int i = 0; i < 2; i++) {
                pa[i] = *reinterpret_cast<const float4*>(
                    A + (long long)(lr + i * 64) * K + k0 + lc);
                pb[i] = *reinterpret_cast<const float4*>(
                    B + (long long)(k0 + brow + i * 8) * N + (long long)bn * BN + bcol);
            }
        }
#pragma unroll
        for (int kk = 0; kk < BK; kk++) {
            float af[8], bf[8];
            *reinterpret_cast<float4*>(&af[0]) = *reinterpret_cast<const float4*>(&As[buf][kk][ty * 4]);
            *reinterpret_cast<float4*>(&af[4]) = *reinterpret_cast<const float4*>(&As[buf][kk][64 + ty * 4]);
            *reinterpret_cast<float4*>(&bf[0]) = *reinterpret_cast<const float4*>(&Bs[buf][kk][tx * 4]);
            *reinterpret_cast<float4*>(&bf[4]) = *reinterpret_cast<const float4*>(&Bs[buf][kk][64 + tx * 4]);
#pragma unroll
            for (int i = 0; i < 8; i++)
#pragma unroll
                for (int j = 0; j < 8; j++)
                    acc[i][j] = fmaf(af[i], bf[j], acc[i][j]);
        }
        if (hasNext) {
            const int nb = buf ^ 1;
#pragma unroll
            for (int i = 0; i < 2; i++) {
                const int r = lr + i * 64;
                As[nb][lc + 0][r] = pa[i].x; As[nb][lc + 1][r] = pa[i].y;
                As[nb][lc + 2][r] = pa[i].z; As[nb][lc + 3][r] = pa[i].w;
                *reinterpret_cast<float4*>(&Bs[nb][brow + i * 8][bcol]) = pb[i];
            }
        }
        __syncthreads();
        buf ^= 1;
    }

    const int rbase = bm * BM, cbase = bn * BN;
#pragma unroll
    for (int i = 0; i < 8; i++) {
        const int r = rbase + ((i < 4) ? (ty * 4 + i) : (64 + ty * 4 + i - 4));
        float4 v0, v1;
        // round-half-even to 4 decimals, exactly as jnp.round(x,4): rint(x*1e4)/1e4
        v0.x = rintf(acc[i][0] * 10000.0f) / 10000.0f;
        v0.y = rintf(acc[i][1] * 10000.0f) / 10000.0f;
        v0.z = rintf(acc[i][2] * 10000.0f) / 10000.0f;
        v0.w = rintf(acc[i][3] * 10000.0f) / 10000.0f;
        v1.x = rintf(acc[i][4] * 10000.0f) / 10000.0f;
        v1.y = rintf(acc[i][5] * 10000.0f) / 10000.0f;
        v1.z = rintf(acc[i][6] * 10000.0f) / 10000.0f;
        v1.w = rintf(acc[i][7] * 10000.0f) / 10000.0f;
        *reinterpret_cast<float4*>(C + (long long)r * N + cbase + tx * 4) = v0;
        *reinterpret_cast<float4*>(C + (long long)r * N + cbase + 64 + tx * 4) = v1;
    }
}

// ---------------------------------------------------------------------------
// Causal softmax over row q (valid length q+1), in place; zero-fills the masked
// tail so the P*V GEMM can run dense tiles. One block (256 thr) per row.
// ---------------------------------------------------------------------------
__global__ void softmax_kernel(float* __restrict__ S)
{
    const int q = blockIdx.x;
    const int b = blockIdx.y;
    float* row = S + ((long long)b * SEQ + q) * (long long)SEQ;
    const int L = q + 1;
    const int t = threadIdx.x;
    const float NEG_INF = __int_as_float(0xff800000u);

    float xv[8];
    float m = NEG_INF;
#pragma unroll
    for (int i = 0; i < 8; i++) {
        const int idx = i * 256 + t;
        xv[i] = (idx < L) ? row[idx] : NEG_INF;
        m = fmaxf(m, xv[i]);
    }
#pragma unroll
    for (int o = 16; o > 0; o >>= 1) m = fmaxf(m, __shfl_xor_sync(0xffffffffu, m, o));

    __shared__ float smax[8], ssum[8];
    if ((t & 31) == 0) smax[t >> 5] = m;
    __syncthreads();
    float mm = smax[0];
#pragma unroll
    for (int w = 1; w < 8; w++) mm = fmaxf(mm, smax[w]);

    float e[8];
    float s = 0.0f;
#pragma unroll
    for (int i = 0; i < 8; i++) { e[i] = expf(xv[i] - mm); s += e[i]; }  // exp(-inf)=0 masks
#pragma unroll
    for (int o = 16; o > 0; o >>= 1) s += __shfl_xor_sync(0xffffffffu, s, o);
    if ((t & 31) == 0) ssum[t >> 5] = s;
    __syncthreads();
    float ss = 0.0f;
#pragma unroll
    for (int w = 0; w < 8; w++) ss += ssum[w];

#pragma unroll
    for (int i = 0; i < 8; i++) {
        const int idx = i * 256 + t;
        row[idx] = (idx < L) ? (e[i] / ss) : 0.0f;
    }
}

// ---------------------------------------------------------------------------
extern "C" void kernel_launch(void* const* d_in, const int* in_sizes, int n_in,
                              void* d_out, int out_size)
{
    const float* X  = (const float*)d_in[0];  // embedded [4,2048,1024]
    const float* Wk = (const float*)d_in[1];  // [1024,1024]
    const float* Wq = (const float*)d_in[2];
    const float* Wv = (const float*)d_in[3];
    float* out = (float*)d_out;               // [4,2048,1024] fp32

    float *Qp, *Kp, *Vp, *Sp;
    cudaGetSymbolAddress((void**)&Qp, g_Q);
    cudaGetSymbolAddress((void**)&Kp, g_K);
    cudaGetSymbolAddress((void**)&Vp, g_V);
    cudaGetSymbolAddress((void**)&Sp, g_S);

    const dim3 blk(256);
    const long long sQKV = (long long)SEQ * ADIM;
    const long long sS   = (long long)SEQ * SEQ;

    // 1-3) Projections: [8192,1024] = X[8192,1024] * W^T (NT GEMM)
    const dim3 gproj(ADIM / 128, (BATCH * SEQ) / 128, 1);
    gemm_nt_kernel<<<gproj, blk>>>(Qp, X, Wq, BATCH * SEQ, ADIM, EMB, 1.0f, 0, 0, 0, 0);
    gemm_nt_kernel<<<gproj, blk>>>(Kp, X, Wk, BATCH * SEQ, ADIM, EMB, 1.0f, 0, 0, 0, 0);
    gemm_nt_kernel<<<gproj, blk>>>(Vp, X, Wv, BATCH * SEQ, ADIM, EMB, 1.0f, 0, 0, 0, 0);

    // 4) Scores: S_b = (1/32) * Q_b * K_b^T, causal tile-skip
    const dim3 gs(SEQ / 128, SEQ / 128, BATCH);
    gemm_nt_kernel<<<gs, blk>>>(Sp, Qp, Kp, SEQ, SEQ, ADIM, 0.03125f, 1, sQKV, sQKV, sS);

    // 5) Causal softmax (in place, zero-fills masked tail)
    softmax_kernel<<<dim3(SEQ, BATCH), blk>>>(Sp);

    // 6) Out = round4(P_b * V_b), causal k-loop truncation
    const dim3 go(ADIM / 128, SEQ / 128, BATCH);
    gemm_nn_round_kernel<<<go, blk>>>(out, Sp, Vp, SEQ, ADIM, SEQ, 1, sS, sQKV, sQKV);
}